// round 17
// baseline (speedup 1.0000x reference)
#include <cuda_runtime.h>

// Problem constants
#define N_PRE       20000
#define VEC_DIM     300
#define INPUT_SIZE  10000
#define HIDDEN      256
#define OUT_DIM     556
#define N_TOKENS    4096
#define VEC4        (VEC_DIM / 4)            // 75

#define N_BUCKETS   313                       // ceil(10000/32)
#define VEC_ITEMS   (N_TOKENS * VEC4)         // 307200
#define B_BLOCKS    ((VEC_ITEMS + 255) / 256) // 1200
#define C_BLOCKS    (N_TOKENS * (HIDDEN/4) / 256) // 1024
#define TOTAL_BLOCKS (N_BUCKETS + B_BLOCKS + C_BLOCKS)

#define LIST_CAP    3968   // smem budget; actual max bucket load ~15 for this data

// Single fused kernel, role by blockIdx.x:
//  [0,313):  bucket gather. Bucket bb owns W columns c in [bb*32, bb*32+32).
//            Scan batch, compact matching tokens (t-N_PRE in bucket) to smem,
//            load the 256x32 W tile ONCE (coalesced, 256 wavefronts), then for
//            each matching token store out[tok][300:556] = tile[c&31][:] + b.
//            Amortizes the divergent gather ~4.4x (one tile : ~4.4 tokens).
//  [313,1513): vector copy, flat float4 items: out[tok][0:300]=vec[t] or 0.
//  [1513,2537): bias fill for t<N_PRE tokens: out[tok][300:556] = b.
__global__ __launch_bounds__(256)
void encoder_all(const int* __restrict__ batch,
                 const float* __restrict__ vectors,
                 const float* __restrict__ W,
                 const float* __restrict__ b,
                 float* __restrict__ out)
{
    // tile[c_off][h]: pad 257 -> LDS tile[off][tid] conflict-free, STS conflict-free
    __shared__ float tile[32][HIDDEN + 1];
    __shared__ int   s_list[LIST_CAP];
    __shared__ int   s_cnt;

    const int bid = blockIdx.x;
    const int tid = threadIdx.x;

    if (bid < N_BUCKETS) {
        // ---------------- role A: bucket gather ----------------
        const int lane = tid & 31;
        if (tid == 0) s_cnt = 0;
        __syncthreads();

        const int c0 = bid * 32;

        // scan batch, warp-ballot compaction of tokens in this bucket
        for (int i = tid; i < N_TOKENS; i += 256) {
            const int  c = batch[i] - N_PRE;
            const bool m = (c >= 0) && ((c >> 5) == bid);
            const unsigned bal = __ballot_sync(0xffffffffu, m);
            int base = 0;
            if (lane == 0 && bal) base = atomicAdd(&s_cnt, __popc(bal));
            base = __shfl_sync(0xffffffffu, base, 0);
            if (m) {
                const int pos = base + __popc(bal & ((1u << lane) - 1u));
                if (pos < LIST_CAP)
                    s_list[pos] = (i << 5) | (c & 31);
            }
        }
        __syncthreads();
        const int cnt = s_cnt;
        if (cnt == 0) return;                 // ~1% of buckets

        // load W tile: 256 rows x 32 cols, coalesced float4 (8 thr/row line)
        const int j4 = (tid & 7) * 4;         // col offset within bucket
        const int c  = c0 + j4;
#pragma unroll
        for (int r0 = 0; r0 < HIDDEN; r0 += 32) {
            const int row = r0 + (tid >> 3);
            float4 v = make_float4(0.f, 0.f, 0.f, 0.f);
            if (c < INPUT_SIZE)               // last bucket is 16 wide
                v = *reinterpret_cast<const float4*>(
                        W + (size_t)row * INPUT_SIZE + c);
            tile[j4 + 0][row] = v.x;          // banks: (j4+row)%32, conflict-free
            tile[j4 + 1][row] = v.y;
            tile[j4 + 2][row] = v.z;
            tile[j4 + 3][row] = v.w;
        }
        const float bias = b[tid];
        __syncthreads();

        // emit: coalesced 1024B store per token
        for (int e = 0; e < cnt; e++) {
            const int ent = s_list[e];
            const int tok = ent >> 5;
            const int off = ent & 31;
            out[(size_t)tok * OUT_DIM + VEC_DIM + tid] = tile[off][tid] + bias;
        }
    } else if (bid < N_BUCKETS + B_BLOCKS) {
        // ---------------- role B: vector copy ----------------
        const int k = (bid - N_BUCKETS) * 256 + tid;
        if (k < VEC_ITEMS) {
            const int tok = k / VEC4;
            const int q   = k - tok * VEC4;
            const int t   = batch[tok];
            float4 v = make_float4(0.f, 0.f, 0.f, 0.f);
            if (t < N_PRE)
                v = reinterpret_cast<const float4*>(
                        vectors + (size_t)t * VEC_DIM)[q];
            reinterpret_cast<float4*>(out + (size_t)tok * OUT_DIM)[q] = v;
        }
    } else {
        // ---------------- role C: bias fill for t < N_PRE ----------------
        const int k   = (bid - N_BUCKETS - B_BLOCKS) * 256 + tid; // < 262144
        const int tok = k >> 6;               // 64 float4 per token
        const int q   = k & 63;
        if (batch[tok] < N_PRE) {
            const float4 bb4 = reinterpret_cast<const float4*>(b)[q];
            reinterpret_cast<float4*>(
                out + (size_t)tok * OUT_DIM + VEC_DIM)[q] = bb4;
        }
    }
}

extern "C" void kernel_launch(void* const* d_in, const int* in_sizes, int n_in,
                              void* d_out, int out_size)
{
    const int*   batch   = (const int*)  d_in[0];
    const float* vectors = (const float*)d_in[1];
    const float* W       = (const float*)d_in[2];
    const float* b       = (const float*)d_in[3];
    float*       out     = (float*)d_out;

    encoder_all<<<TOTAL_BLOCKS, 256>>>(batch, vectors, W, b, out);
}